// round 16
// baseline (speedup 1.0000x reference)
#include <cuda_runtime.h>
#include <cstdint>

#define T_STEPS 512
#define BATCH   4096
#define DIN     4
#define HID     32
#define NB      8              // batch elements per group
#define BP      (NB / 2)       // batch-pairs
#define GROUPS  4              // groups per block; group g = SMSP g (P, CA, CB warps)
#define THREADS (GROUPS * 96)            // 384: 4 producers + 4 consumerA + 4 consumerB
#define NBLOCKS (BATCH / (GROUPS * NB))  // 128
#define WHH0_REG 12            // producer: whh0 k-slices cached in registers

typedef unsigned long long u64;

struct __align__(16) Smem {
    // packed gate weights: [k][u] = (Wi*.5, Wf*.5, Wg, Wo*.5)
    float4 whh0[HID][HID];   // 16 KB
    float4 wih1[HID][HID];   // 16 KB
    float4 whh1[HID][HID];   // 16 KB
    float4 wih0[DIN][HID];   //  2 KB
    float4 bias0[HID];
    float4 bias1[HID];
    // h1 handoff: per-group double-buffered, natural batch-pairs
    u64 h1buf[GROUPS][2][HID][BP];   // 8 KB
    // h2 state (written by CB, read by CA+CB)
    u64 h2s[GROUPS][HID][BP];        // 4 KB
    // CA->CB handoff: sig(i),sig(f) pairs; [j][lane], j = bp (si) / 4+bp (sf)
    u64 part[GROUPS][2][8][32];      // 16 KB
    unsigned long long mb_if[GROUPS];  // mbarrier: CA's if-data ready (count 1/step)
    unsigned long long mb_h2[GROUPS];  // mbarrier: CB's h2(t) ready
    float wout[HID];
    float bout;
};

__device__ __forceinline__ u64 pk2(float lo, float hi) {
    u64 r; asm("mov.b64 %0,{%1,%2};" : "=l"(r) : "f"(lo), "f"(hi)); return r;
}
__device__ __forceinline__ void upk2(u64 v, float& lo, float& hi) {
    asm("mov.b64 {%0,%1},%2;" : "=f"(lo), "=f"(hi) : "l"(v));
}
__device__ __forceinline__ u64 ffma2(u64 a, u64 b, u64 c) {
    u64 d; asm("fma.rn.f32x2 %0,%1,%2,%3;" : "=l"(d) : "l"(a), "l"(b), "l"(c)); return d;
}
__device__ __forceinline__ float tanh_ap(float x) {
    float y; asm("tanh.approx.f32 %0,%1;" : "=f"(y) : "f"(x)); return y;
}
// weights pre-scaled by 0.5 for sigmoid gates
__device__ __forceinline__ float sig_pre(float x) { return fmaf(tanh_ap(x), 0.5f, 0.5f); }

__device__ __forceinline__ void bar_sync96(int id) {
    asm volatile("bar.sync %0, 96;" :: "r"(id) : "memory");
}
__device__ __forceinline__ void bar_arrive96(int id) {
    asm volatile("bar.arrive %0, 96;" :: "r"(id) : "memory");
}
__device__ __forceinline__ uint32_t smem_u32(const void* p) {
    uint32_t a;
    asm("{ .reg .u64 t; cvta.to.shared.u64 t, %1; cvt.u32.u64 %0, t; }" : "=r"(a) : "l"(p));
    return a;
}
__device__ __forceinline__ void mbar_init(uint32_t addr, uint32_t cnt) {
    asm volatile("mbarrier.init.shared.b64 [%0], %1;" :: "r"(addr), "r"(cnt) : "memory");
}
__device__ __forceinline__ void mbar_arrive(uint32_t addr) {
    asm volatile("mbarrier.arrive.shared.b64 _, [%0];" :: "r"(addr) : "memory");
}
__device__ __forceinline__ void mbar_wait(uint32_t addr, uint32_t parity) {
    asm volatile(
        "{\n\t.reg .pred p;\n\t"
        "LAB%=:\n\t"
        "mbarrier.try_wait.parity.acquire.cta.shared::cta.b64 p, [%0], %1;\n\t"
        "@p bra DONE%=;\n\t"
        "bra LAB%=;\n\t"
        "DONE%=:\n\t}"
        :: "r"(addr), "r"(parity) : "memory");
}

// 4-gate k-slice (producer): weights (wi,wf),(wg,wo), 4 batch-pairs
#define GATE_K4R(WX, WY, HV)                                                  \
    do {                                                                      \
        float wi_, wf_, wg_, wo_;                                             \
        upk2((WX), wi_, wf_); upk2((WY), wg_, wo_);                           \
        u64 wii_ = pk2(wi_, wi_), wff_ = pk2(wf_, wf_);                       \
        u64 wgg_ = pk2(wg_, wg_), woo_ = pk2(wo_, wo_);                       \
        _Pragma("unroll")                                                     \
        for (int bp = 0; bp < BP; ++bp) {                                     \
            ai[bp] = ffma2(wii_, (HV)[bp], ai[bp]);                           \
            af[bp] = ffma2(wff_, (HV)[bp], af[bp]);                           \
            ag[bp] = ffma2(wgg_, (HV)[bp], ag[bp]);                           \
            ao[bp] = ffma2(woo_, (HV)[bp], ao[bp]);                           \
        }                                                                     \
    } while (0)

// 2-gate k-slice (consumers): one u64 weight pair (wa,wb), 4 batch-pairs
#define GATE_K2(WAB, HV)                                                      \
    do {                                                                      \
        float wa_, wb_;                                                       \
        upk2((WAB), wa_, wb_);                                                \
        u64 waa_ = pk2(wa_, wa_), wbb_ = pk2(wb_, wb_);                       \
        _Pragma("unroll")                                                     \
        for (int bp = 0; bp < BP; ++bp) {                                     \
            aA[bp] = ffma2(waa_, (HV)[bp], aA[bp]);                           \
            aB[bp] = ffma2(wbb_, (HV)[bp], aB[bp]);                           \
        }                                                                     \
    } while (0)

__global__ void __launch_bounds__(THREADS, 1) lstm2_kernel(
    const float* __restrict__ x,
    const float* __restrict__ Wih0, const float* __restrict__ Whh0,
    const float* __restrict__ bih0, const float* __restrict__ bhh0,
    const float* __restrict__ Wih1, const float* __restrict__ Whh1,
    const float* __restrict__ bih1, const float* __restrict__ bhh1,
    const float* __restrict__ Wout, const float* __restrict__ boutp,
    float* __restrict__ out)
{
    extern __shared__ unsigned char smem_raw[];
    Smem* s = reinterpret_cast<Smem*>(smem_raw);

    const int tid  = threadIdx.x;
    const int w    = tid >> 5;
    const int lane = tid & 31;
    const int role = w >> 2;     // 0 = producer, 1 = consumerA (i,f), 2 = consumerB (g,o)
    const int grp  = w & 3;      // SMSP index; all 3 roles of a group share an SMSP

    // ---- stage packed weights (i/f/o rows pre-scaled by 0.5) ----
    for (int i = tid; i < HID * HID; i += THREADS) {
        int k = i >> 5, u = i & 31;
        s->whh0[k][u] = make_float4(0.5f * Whh0[u * HID + k],  0.5f * Whh0[(32 + u) * HID + k],
                                    Whh0[(64 + u) * HID + k],  0.5f * Whh0[(96 + u) * HID + k]);
        s->wih1[k][u] = make_float4(0.5f * Wih1[u * HID + k],  0.5f * Wih1[(32 + u) * HID + k],
                                    Wih1[(64 + u) * HID + k],  0.5f * Wih1[(96 + u) * HID + k]);
        s->whh1[k][u] = make_float4(0.5f * Whh1[u * HID + k],  0.5f * Whh1[(32 + u) * HID + k],
                                    Whh1[(64 + u) * HID + k],  0.5f * Whh1[(96 + u) * HID + k]);
    }
    for (int i = tid; i < DIN * HID; i += THREADS) {
        int k = i >> 5, u = i & 31;
        s->wih0[k][u] = make_float4(0.5f * Wih0[u * DIN + k],  0.5f * Wih0[(32 + u) * DIN + k],
                                    Wih0[(64 + u) * DIN + k],  0.5f * Wih0[(96 + u) * DIN + k]);
    }
    if (tid < HID) {
        int u = tid;
        s->bias0[u] = make_float4(0.5f * (bih0[u] + bhh0[u]),        0.5f * (bih0[32 + u] + bhh0[32 + u]),
                                  bih0[64 + u] + bhh0[64 + u],       0.5f * (bih0[96 + u] + bhh0[96 + u]));
        s->bias1[u] = make_float4(0.5f * (bih1[u] + bhh1[u]),        0.5f * (bih1[32 + u] + bhh1[32 + u]),
                                  bih1[64 + u] + bhh1[64 + u],       0.5f * (bih1[96 + u] + bhh1[96 + u]));
        s->wout[u] = Wout[u];
        if (u == 0) s->bout = boutp[0];
    }
    {
        u64* z = &s->h1buf[0][0][0][0];
        for (int i = tid; i < GROUPS * 2 * HID * BP; i += THREADS) z[i] = 0ull;
        u64* z2 = &s->h2s[0][0][0];
        for (int i = tid; i < GROUPS * HID * BP; i += THREADS) z2[i] = 0ull;
    }
    if (tid == 0) {
        #pragma unroll
        for (int g = 0; g < GROUPS; ++g) {
            mbar_init(smem_u32(&s->mb_if[g]), 1);
            mbar_init(smem_u32(&s->mb_h2[g]), 1);
        }
    }
    __syncthreads();

    const int batch0 = (blockIdx.x * GROUPS + grp) * NB;
    // named barriers per group: full = grp*4+{0,1}, empty = grp*4+{2,3}  (16 total)
    const int bf0 = grp * 4 + 0, bf1 = grp * 4 + 1;
    const int be0 = grp * 4 + 2, be1 = grp * 4 + 3;
    const uint32_t mbif = smem_u32(&s->mb_if[grp]);
    const uint32_t mbh2 = smem_u32(&s->mb_h2[grp]);

    if (role == 0) {
        // ================= producer: layer 1 =================
        const float* xbase = x + (size_t)batch0 * T_STEPS * DIN;
        u64 ai[BP], af[BP], ag[BP], ao[BP];

        float c1[NB];
        #pragma unroll
        for (int b = 0; b < NB; ++b) c1[b] = 0.0f;

        const float4 b0v = s->bias0[lane];
        const u64 bI = pk2(b0v.x, b0v.x), bF = pk2(b0v.y, b0v.y);
        const u64 bG = pk2(b0v.z, b0v.z), bO = pk2(b0v.w, b0v.w);

        u64 w0x[DIN][2];
        #pragma unroll
        for (int k = 0; k < DIN; ++k) {
            ulonglong2 wp = *reinterpret_cast<const ulonglong2*>(&s->wih0[k][lane]);
            w0x[k][0] = wp.x; w0x[k][1] = wp.y;
        }
        u64 wr0[WHH0_REG][2];
        #pragma unroll
        for (int k = 0; k < WHH0_REG; ++k) {
            ulonglong2 wp = *reinterpret_cast<const ulonglong2*>(&s->whh0[k][lane]);
            wr0[k][0] = wp.x; wr0[k][1] = wp.y;
        }

        float4 xf[NB];
        #pragma unroll
        for (int b = 0; b < NB; ++b)
            xf[b] = *reinterpret_cast<const float4*>(xbase + (size_t)b * T_STEPS * DIN);

        for (int t = 0; t < T_STEPS; ++t) {
            const int buf = t & 1;
            if (t >= 2) bar_sync96(buf ? be1 : be0);   // CA+CB done reading this buffer

            #pragma unroll
            for (int bp = 0; bp < BP; ++bp) { ai[bp] = bI; af[bp] = bF; ag[bp] = bG; ao[bp] = bO; }

            {   // x contribution (register weights)
                u64 hv[BP];
                #pragma unroll
                for (int bp = 0; bp < BP; ++bp) hv[bp] = pk2(xf[2*bp].x, xf[2*bp+1].x);
                GATE_K4R(w0x[0][0], w0x[0][1], hv);
                #pragma unroll
                for (int bp = 0; bp < BP; ++bp) hv[bp] = pk2(xf[2*bp].y, xf[2*bp+1].y);
                GATE_K4R(w0x[1][0], w0x[1][1], hv);
                #pragma unroll
                for (int bp = 0; bp < BP; ++bp) hv[bp] = pk2(xf[2*bp].z, xf[2*bp+1].z);
                GATE_K4R(w0x[2][0], w0x[2][1], hv);
                #pragma unroll
                for (int bp = 0; bp < BP; ++bp) hv[bp] = pk2(xf[2*bp].w, xf[2*bp+1].w);
                GATE_K4R(w0x[3][0], w0x[3][1], hv);
            }
            if (t + 1 < T_STEPS) {
                const float* xt = xbase + (size_t)(t + 1) * DIN;
                #pragma unroll
                for (int b = 0; b < NB; ++b)
                    xf[b] = *reinterpret_cast<const float4*>(xt + (size_t)b * T_STEPS * DIN);
            }

            {   // recurrent: h1(t-1) from other buffer
                const u64* hp = &s->h1buf[grp][buf ^ 1][0][0];
                #pragma unroll
                for (int k = 0; k < WHH0_REG; ++k) {
                    const ulonglong2 hA = *reinterpret_cast<const ulonglong2*>(hp + k * BP);
                    const ulonglong2 hB = *reinterpret_cast<const ulonglong2*>(hp + k * BP + 2);
                    u64 hv[BP] = { hA.x, hA.y, hB.x, hB.y };
                    GATE_K4R(wr0[k][0], wr0[k][1], hv);
                }
                #pragma unroll
                for (int k = WHH0_REG; k < HID; ++k) {
                    const ulonglong2 wp = *reinterpret_cast<const ulonglong2*>(&s->whh0[k][lane]);
                    const ulonglong2 hA = *reinterpret_cast<const ulonglong2*>(hp + k * BP);
                    const ulonglong2 hB = *reinterpret_cast<const ulonglong2*>(hp + k * BP + 2);
                    u64 hv[BP] = { hA.x, hA.y, hB.x, hB.y };
                    GATE_K4R(wp.x, wp.y, hv);
                }
            }

            #pragma unroll
            for (int bp = 0; bp < BP; ++bp) {
                float i0, i1, f0, f1, g0, g1, o0, o1;
                upk2(ai[bp], i0, i1); upk2(af[bp], f0, f1);
                upk2(ag[bp], g0, g1); upk2(ao[bp], o0, o1);
                float ca = sig_pre(f0) * c1[2*bp]   + sig_pre(i0) * tanh_ap(g0);
                float cb = sig_pre(f1) * c1[2*bp+1] + sig_pre(i1) * tanh_ap(g1);
                c1[2*bp]   = ca;  c1[2*bp+1] = cb;
                s->h1buf[grp][buf][lane][bp] = pk2(sig_pre(o0) * tanh_ap(ca),
                                                   sig_pre(o1) * tanh_ap(cb));
            }
            __syncwarp();
            __threadfence_block();
            bar_arrive96(buf ? bf1 : bf0);   // h1(t) published
        }
    } else if (role == 1) {
        // ================= consumerA: layer-2 gates i,f =================
        u64 aA[BP], aB[BP];   // i, f accumulators

        const float4 b1v = s->bias1[lane];
        const u64 bI = pk2(b1v.x, b1v.x), bF = pk2(b1v.y, b1v.y);

        // register-cache whh1 (i,f) half: low u64 of each slice
        u64 wca[HID];
        #pragma unroll
        for (int k = 0; k < HID; ++k)
            wca[k] = *reinterpret_cast<const u64*>(&s->whh1[k][lane]);   // (wi,wf)

        for (int t = 0; t < T_STEPS; ++t) {
            const int buf = t & 1;
            bar_sync96(buf ? bf1 : bf0);     // h1(t) ready
            if (t >= 1) mbar_wait(mbh2, (t - 1) & 1);   // h2(t-1) ready

            #pragma unroll
            for (int bp = 0; bp < BP; ++bp) { aA[bp] = bI; aB[bp] = bF; }

            {   // Wih1(i,f)·h1(t) (smem weights) + Whh1(i,f)·h2(t-1) (reg weights)
                const u64* hp  = &s->h1buf[grp][buf][0][0];
                const u64* h2p = &s->h2s[grp][0][0];
                #pragma unroll
                for (int k = 0; k < HID; ++k) {
                    {
                        const u64 wab = *reinterpret_cast<const u64*>(&s->wih1[k][lane]);  // (wi,wf)
                        const ulonglong2 hA = *reinterpret_cast<const ulonglong2*>(hp + k * BP);
                        const ulonglong2 hB = *reinterpret_cast<const ulonglong2*>(hp + k * BP + 2);
                        u64 hv[BP] = { hA.x, hA.y, hB.x, hB.y };
                        GATE_K2(wab, hv);
                    }
                    {
                        const ulonglong2 hA = *reinterpret_cast<const ulonglong2*>(h2p + k * BP);
                        const ulonglong2 hB = *reinterpret_cast<const ulonglong2*>(h2p + k * BP + 2);
                        u64 hv[BP] = { hA.x, hA.y, hB.x, hB.y };
                        GATE_K2(wca[k], hv);
                    }
                }
            }
            bar_arrive96(buf ? be1 : be0);   // h1 buffer consumed (by CA)

            // activations: sig(i), sig(f) -> smem handoff
            #pragma unroll
            for (int bp = 0; bp < BP; ++bp) {
                float i0, i1, f0, f1;
                upk2(aA[bp], i0, i1); upk2(aB[bp], f0, f1);
                s->part[grp][buf][bp][lane]     = pk2(sig_pre(i0), sig_pre(i1));
                s->part[grp][buf][4 + bp][lane] = pk2(sig_pre(f0), sig_pre(f1));
            }
            __syncwarp();
            __threadfence_block();
            if (lane == 0) mbar_arrive(mbif);
        }
    } else {
        // ================= consumerB: layer-2 gates g,o + state =================
        u64 aA[BP], aB[BP];   // g, o accumulators
        float c2[NB], h2v[NB];
        #pragma unroll
        for (int b = 0; b < NB; ++b) { c2[b] = 0.0f; h2v[b] = 0.0f; }

        const float4 b1v = s->bias1[lane];
        const u64 bG = pk2(b1v.z, b1v.z), bO = pk2(b1v.w, b1v.w);

        // register-cache whh1 (g,o) half: high u64 of each slice
        u64 wcb[HID];
        #pragma unroll
        for (int k = 0; k < HID; ++k)
            wcb[k] = *(reinterpret_cast<const u64*>(&s->whh1[k][lane]) + 1);   // (wg,wo)

        for (int t = 0; t < T_STEPS; ++t) {
            const int buf = t & 1;
            bar_sync96(buf ? bf1 : bf0);     // h1(t) ready

            #pragma unroll
            for (int bp = 0; bp < BP; ++bp) { aA[bp] = bG; aB[bp] = bO; }

            {   // Wih1(g,o)·h1(t) + Whh1(g,o)·h2(t-1)
                const u64* hp  = &s->h1buf[grp][buf][0][0];
                const u64* h2p = &s->h2s[grp][0][0];
                #pragma unroll
                for (int k = 0; k < HID; ++k) {
                    {
                        const u64 wab = *(reinterpret_cast<const u64*>(&s->wih1[k][lane]) + 1);  // (wg,wo)
                        const ulonglong2 hA = *reinterpret_cast<const ulonglong2*>(hp + k * BP);
                        const ulonglong2 hB = *reinterpret_cast<const ulonglong2*>(hp + k * BP + 2);
                        u64 hv[BP] = { hA.x, hA.y, hB.x, hB.y };
                        GATE_K2(wab, hv);
                    }
                    {
                        const ulonglong2 hA = *reinterpret_cast<const ulonglong2*>(h2p + k * BP);
                        const ulonglong2 hB = *reinterpret_cast<const ulonglong2*>(h2p + k * BP + 2);
                        u64 hv[BP] = { hA.x, hA.y, hB.x, hB.y };
                        GATE_K2(wcb[k], hv);
                    }
                }
            }

            // wait for CA's sigmoids, then read them
            mbar_wait(mbif, t & 1);
            u64 si[BP], sf[BP];
            #pragma unroll
            for (int bp = 0; bp < BP; ++bp) {
                si[bp] = s->part[grp][buf][bp][lane];
                sf[bp] = s->part[grp][buf][4 + bp][lane];
            }
            bar_arrive96(buf ? be1 : be0);   // h1 buffer + part consumed (by CB)

            // c2/h2 update
            #pragma unroll
            for (int bp = 0; bp < BP; ++bp) {
                float g0, g1, o0, o1, s0, s1, f0, f1;
                upk2(aA[bp], g0, g1); upk2(aB[bp], o0, o1);
                upk2(si[bp], s0, s1); upk2(sf[bp], f0, f1);
                float ca = f0 * c2[2*bp]   + s0 * tanh_ap(g0);
                float cb = f1 * c2[2*bp+1] + s1 * tanh_ap(g1);
                c2[2*bp]   = ca;  c2[2*bp+1] = cb;
                h2v[2*bp]   = sig_pre(o0) * tanh_ap(ca);
                h2v[2*bp+1] = sig_pre(o1) * tanh_ap(cb);
                s->h2s[grp][lane][bp] = pk2(h2v[2*bp], h2v[2*bp+1]);
            }
            __syncwarp();
            __threadfence_block();
            if (lane == 0) mbar_arrive(mbh2);   // h2(t) published
        }

        // ---- output head ----
        const float wo = s->wout[lane];
        #pragma unroll
        for (int b = 0; b < NB; ++b) {
            float v = h2v[b] * wo;
            #pragma unroll
            for (int off = 16; off; off >>= 1) v += __shfl_xor_sync(0xffffffffu, v, off);
            if (lane == 0) out[batch0 + b] = v + s->bout;
        }
    }
}

extern "C" void kernel_launch(void* const* d_in, const int* in_sizes, int n_in,
                              void* d_out, int out_size)
{
    (void)in_sizes; (void)n_in; (void)out_size;
    const size_t smem = sizeof(Smem);
    cudaFuncSetAttribute(lstm2_kernel, cudaFuncAttributeMaxDynamicSharedMemorySize, (int)smem);
    lstm2_kernel<<<NBLOCKS, THREADS, smem>>>(
        (const float*)d_in[0],
        (const float*)d_in[1], (const float*)d_in[2],
        (const float*)d_in[3], (const float*)d_in[4],
        (const float*)d_in[5], (const float*)d_in[6],
        (const float*)d_in[7], (const float*)d_in[8],
        (const float*)d_in[9], (const float*)d_in[10],
        (float*)d_out);
}